// round 5
// baseline (speedup 1.0000x reference)
#include <cuda_runtime.h>
#include <cstdint>

#define HID 128
#define NMAX 100000
#define EMAX 3200000

// ---- static scratch (no allocation allowed) ----
__device__ __align__(128) float g_H[NMAX * HID];     // transformed rows (dinv-prescaled)
__device__ __align__(128) float g_H1[NMAX * HID];    // h1 after layer-1 gather
__device__ __align__(128) float g_W2[HID * HID];     // [Wm | Wv]
__device__ __align__(128) float g_b2[HID];           // [bm | bv]
__device__ float g_dinv[NMAX];
__device__ int   g_cnt[NMAX];
__device__ int   g_rowptr[NMAX + 1];
__device__ int   g_cursor[NMAX];
__device__ int   g_csrc[EMAX];
__device__ int   g_is64;

// ---------------- dtype detection ----------------
// int64 edge data (values < 2^31) viewed as int32 is [v0,0,v1,0,...]:
// all odd words zero. int32 data: odd words are random node ids.
__global__ void k_detect(const int* __restrict__ EI32) {
    int v = EI32[threadIdx.x * 2 + 1];
    unsigned nz = __ballot_sync(0xffffffffu, v != 0);
    if (threadIdx.x == 0) g_is64 = (nz == 0) ? 1 : 0;
}

__device__ __forceinline__ int edge_read(const void* EI, int idx) {
    if (g_is64) return (int)((const long long*)EI)[idx];
    return ((const int*)EI)[idx];
}

// ---------------- utility kernels ----------------

__global__ void k_zero_int(int* __restrict__ p, int n) {
    int i = blockIdx.x * blockDim.x + threadIdx.x;
    if (i < n) p[i] = 0;
}

__global__ void k_count(const void* __restrict__ EI, int* __restrict__ cnt, int E, int N) {
    int e = blockIdx.x * blockDim.x + threadIdx.x;
    if (e >= E) return;
    int d = edge_read(EI, E + e);   // dst row
    if ((unsigned)d < (unsigned)N) atomicAdd(&cnt[d], 1);
}

// exclusive prefix sum over cnt[0..N-1] -> rowptr[0..N]; single block, 1024 threads
__global__ __launch_bounds__(1024) void k_scan(const int* __restrict__ cnt,
                                               int* __restrict__ rowptr, int N) {
    __shared__ int warpsum[32];
    __shared__ int warpoff[32];
    __shared__ int chunk_total;
    __shared__ int carry;
    int t = threadIdx.x, lane = t & 31, wid = t >> 5;
    if (t == 0) carry = 0;
    __syncthreads();
    for (int base = 0; base < N + 1; base += 1024) {
        int i = base + t;
        int v = (i < N) ? cnt[i] : 0;
        int incl = v;
#pragma unroll
        for (int off = 1; off < 32; off <<= 1) {
            int x = __shfl_up_sync(0xffffffffu, incl, off);
            if (lane >= off) incl += x;
        }
        if (lane == 31) warpsum[wid] = incl;
        __syncthreads();
        if (wid == 0) {
            int ws = warpsum[lane];
            int wi = ws;
#pragma unroll
            for (int off = 1; off < 32; off <<= 1) {
                int x = __shfl_up_sync(0xffffffffu, wi, off);
                if (lane >= off) wi += x;
            }
            warpoff[lane] = wi - ws;  // exclusive warp offsets
            if (lane == 31) chunk_total = wi;
        }
        __syncthreads();
        int excl = incl - v + warpoff[wid];
        if (i <= N) rowptr[i] = carry + excl;
        int total = chunk_total;
        __syncthreads();
        if (t == 0) carry += total;
        __syncthreads();
    }
}

__global__ void k_copy_int(const int* __restrict__ a, int* __restrict__ b, int n) {
    int i = blockIdx.x * blockDim.x + threadIdx.x;
    if (i < n) b[i] = a[i];
}

__global__ void k_fill(const void* __restrict__ EI, int* __restrict__ cursor,
                       int* __restrict__ csrc, int E, int N) {
    int e = blockIdx.x * blockDim.x + threadIdx.x;
    if (e >= E) return;
    int s = edge_read(EI, e);        // src row
    int d = edge_read(EI, E + e);    // dst row
    if ((unsigned)d >= (unsigned)N || (unsigned)s >= (unsigned)N) return;
    int pos = atomicAdd(&cursor[d], 1);
    if ((unsigned)pos < (unsigned)EMAX) csrc[pos] = s;
}

__global__ void k_dinv(const int* __restrict__ cnt, float* __restrict__ dinv, int N) {
    int i = blockIdx.x * blockDim.x + threadIdx.x;
    if (i < N) dinv[i] = rsqrtf((float)cnt[i] + 1.0f);  // +1 self-loop
}

__global__ void k_pack_w2(const float* __restrict__ Wm, const float* __restrict__ bm,
                          const float* __restrict__ Wv, const float* __restrict__ bv,
                          float* __restrict__ W2, float* __restrict__ b2) {
    int idx = blockIdx.x * blockDim.x + threadIdx.x;
    if (idx < HID * HID) {
        int k = idx >> 7, j = idx & 127;
        W2[idx] = (j < 64) ? Wm[k * 64 + j] : Wv[k * 64 + (j - 64)];
    }
    if (idx < HID) b2[idx] = (idx < 64) ? bm[idx] : bv[idx - 64];
}

// ---------------- fused GEMM: C[i,:] = dinv[i] * (A[i,:] @ B), Nout=128 ----------------
// BM=64, BN=128, BK=16, 256 threads, 8x4 micro-tile.

template <int K>
__global__ __launch_bounds__(256) void k_gemm128_scaled(
    const float* __restrict__ A, const float* __restrict__ B,
    const float* __restrict__ dinv, float* __restrict__ C, int M)
{
    __shared__ float As[16][64];
    __shared__ float Bs[16][128];

    int t  = threadIdx.x;
    int r0 = blockIdx.x * 64;
    int tx = t & 31;
    int ty = t >> 5;

    int ai = t >> 2;
    int ak = (t & 3) * 4;
    int bk = t >> 5;
    int bj = (t & 31) * 4;

    float acc[8][4];
#pragma unroll
    for (int i = 0; i < 8; i++)
#pragma unroll
        for (int j = 0; j < 4; j++) acc[i][j] = 0.0f;

    for (int k0 = 0; k0 < K; k0 += 16) {
        int row = r0 + ai;
        float4 av = make_float4(0.f, 0.f, 0.f, 0.f);
        if (row < M)
            av = *reinterpret_cast<const float4*>(&A[(size_t)row * K + k0 + ak]);
        As[ak + 0][ai] = av.x;
        As[ak + 1][ai] = av.y;
        As[ak + 2][ai] = av.z;
        As[ak + 3][ai] = av.w;

        *reinterpret_cast<float4*>(&Bs[bk][bj]) =
            *reinterpret_cast<const float4*>(&B[(size_t)(k0 + bk) * 128 + bj]);
        *reinterpret_cast<float4*>(&Bs[bk + 8][bj]) =
            *reinterpret_cast<const float4*>(&B[(size_t)(k0 + bk + 8) * 128 + bj]);

        __syncthreads();

#pragma unroll
        for (int kk = 0; kk < 16; kk++) {
            float4 a0 = *reinterpret_cast<const float4*>(&As[kk][ty * 8]);
            float4 a1 = *reinterpret_cast<const float4*>(&As[kk][ty * 8 + 4]);
            float4 b  = *reinterpret_cast<const float4*>(&Bs[kk][tx * 4]);
            float a[8] = {a0.x, a0.y, a0.z, a0.w, a1.x, a1.y, a1.z, a1.w};
            float bb[4] = {b.x, b.y, b.z, b.w};
#pragma unroll
            for (int i = 0; i < 8; i++)
#pragma unroll
                for (int j = 0; j < 4; j++)
                    acc[i][j] = fmaf(a[i], bb[j], acc[i][j]);
        }
        __syncthreads();
    }

#pragma unroll
    for (int i = 0; i < 8; i++) {
        int row = r0 + ty * 8 + i;
        if (row < M) {
            float s = dinv[row];
            float4 v = make_float4(acc[i][0] * s, acc[i][1] * s, acc[i][2] * s, acc[i][3] * s);
            *reinterpret_cast<float4*>(&C[(size_t)row * HID + tx * 4]) = v;
        }
    }
}

// ---------------- gather aggregation + fused epilogue ----------------
// One warp per destination node. acc = Hs[d] (self loop) + sum Hs[src].
// MODE 0: out[d,:] = relu(acc*dinv[d] + bias)  (row-major N x 128)
// MODE 1: split write: cols [0,64) -> out[d*64..], cols [64,128) -> out[N*64 + d*64..]

template <int MODE>
__global__ __launch_bounds__(256) void k_gather(
    const int* __restrict__ rowptr, const int* __restrict__ csrc,
    const float* __restrict__ Hs, const float* __restrict__ dinv,
    const float* __restrict__ bias, float* __restrict__ out, int N)
{
    int w = (blockIdx.x * blockDim.x + threadIdx.x) >> 5;
    int lane = threadIdx.x & 31;
    if (w >= N) return;

    const float4* Hs4 = reinterpret_cast<const float4*>(Hs);
    float4 acc = Hs4[(size_t)w * 32 + lane];  // self loop

    int beg = rowptr[w], end = rowptr[w + 1];
    int e = beg;
    for (; e + 4 <= end; e += 4) {
        int s0 = csrc[e], s1 = csrc[e + 1], s2 = csrc[e + 2], s3 = csrc[e + 3];
        float4 v0 = Hs4[(size_t)s0 * 32 + lane];
        float4 v1 = Hs4[(size_t)s1 * 32 + lane];
        float4 v2 = Hs4[(size_t)s2 * 32 + lane];
        float4 v3 = Hs4[(size_t)s3 * 32 + lane];
        acc.x += v0.x + v1.x + v2.x + v3.x;
        acc.y += v0.y + v1.y + v2.y + v3.y;
        acc.z += v0.z + v1.z + v2.z + v3.z;
        acc.w += v0.w + v1.w + v2.w + v3.w;
    }
    for (; e < end; e++) {
        int s = csrc[e];
        float4 v = Hs4[(size_t)s * 32 + lane];
        acc.x += v.x; acc.y += v.y; acc.z += v.z; acc.w += v.w;
    }

    float sc = dinv[w];
    float4 b = reinterpret_cast<const float4*>(bias)[lane];
    float4 r;
    r.x = fmaf(acc.x, sc, b.x);
    r.y = fmaf(acc.y, sc, b.y);
    r.z = fmaf(acc.z, sc, b.z);
    r.w = fmaf(acc.w, sc, b.w);

    if (MODE == 0) {
        r.x = fmaxf(r.x, 0.f); r.y = fmaxf(r.y, 0.f);
        r.z = fmaxf(r.z, 0.f); r.w = fmaxf(r.w, 0.f);
        reinterpret_cast<float4*>(out)[(size_t)w * 32 + lane] = r;
    } else {
        int j0 = lane * 4;
        if (j0 < 64) {
            *reinterpret_cast<float4*>(&out[(size_t)w * 64 + j0]) = r;
        } else {
            *reinterpret_cast<float4*>(&out[(size_t)N * 64 + (size_t)w * 64 + (j0 - 64)]) = r;
        }
    }
}

// ---------------- launch ----------------

extern "C" void kernel_launch(void* const* d_in, const int* in_sizes, int n_in,
                              void* d_out, int out_size)
{
    const float* X  = (const float*)d_in[0];
    const void*  EI = d_in[1];                    // int32 or int64, autodetected
    const float* W1 = (const float*)d_in[2];
    const float* b1 = (const float*)d_in[3];
    const float* Wm = (const float*)d_in[4];
    const float* bm = (const float*)d_in[5];
    const float* Wv = (const float*)d_in[6];
    const float* bv = (const float*)d_in[7];
    float*       out = (float*)d_out;

    int N = in_sizes[0] / 512;
    int E = in_sizes[1] / 2;

    float *p_H, *p_H1, *p_W2, *p_b2, *p_dinv;
    int *p_cnt, *p_rowptr, *p_cursor, *p_csrc;
    cudaGetSymbolAddress((void**)&p_H,      g_H);
    cudaGetSymbolAddress((void**)&p_H1,     g_H1);
    cudaGetSymbolAddress((void**)&p_W2,     g_W2);
    cudaGetSymbolAddress((void**)&p_b2,     g_b2);
    cudaGetSymbolAddress((void**)&p_dinv,   g_dinv);
    cudaGetSymbolAddress((void**)&p_cnt,    g_cnt);
    cudaGetSymbolAddress((void**)&p_rowptr, g_rowptr);
    cudaGetSymbolAddress((void**)&p_cursor, g_cursor);
    cudaGetSymbolAddress((void**)&p_csrc,   g_csrc);

    dim3 blk(256);

    // ---- dtype detect + CSR build + degrees ----
    k_detect<<<1, 32>>>((const int*)EI);
    k_zero_int<<<(N + 255) / 256, blk>>>(p_cnt, N);
    k_count<<<(E + 255) / 256, blk>>>(EI, p_cnt, E, N);
    k_scan<<<1, 1024>>>(p_cnt, p_rowptr, N);
    k_copy_int<<<(N + 255) / 256, blk>>>(p_rowptr, p_cursor, N);
    k_fill<<<(E + 255) / 256, blk>>>(EI, p_cursor, p_csrc, E, N);
    k_dinv<<<(N + 255) / 256, blk>>>(p_cnt, p_dinv, N);
    k_pack_w2<<<(HID * HID + 255) / 256, blk>>>(Wm, bm, Wv, bv, p_W2, p_b2);

    // ---- Layer 1: Hs = dinv * (X @ W1); h1 = relu(gather(Hs)*dinv + b1) ----
    k_gemm128_scaled<512><<<(N + 63) / 64, blk>>>(X, W1, p_dinv, p_H, N);
    k_gather<0><<<(N * 32 + 255) / 256, blk>>>(p_rowptr, p_csrc, p_H, p_dinv, b1, p_H1, N);

    // ---- Layer 2 (mean|var fused): Hs2 = dinv * (h1 @ W2); out = gather(Hs2)*dinv + b2 ----
    k_gemm128_scaled<128><<<(N + 63) / 64, blk>>>(p_H1, p_W2, p_dinv, p_H, N);
    k_gather<1><<<(N * 32 + 255) / 256, blk>>>(p_rowptr, p_csrc, p_H, p_dinv, p_b2, out, N);
}

// round 7
// speedup vs baseline: 1.1206x; 1.1206x over previous
#include <cuda_runtime.h>
#include <cstdint>

#define HID 128
#define NMAX 100000
#define EMAX 3200000

// ---- static scratch (no allocation allowed) ----
__device__ __align__(128) float g_H[NMAX * HID];      // transformed rows (dinv-prescaled)
__device__ __align__(128) float g_H1[NMAX * HID];     // h1 after layer-1 gather
__device__ __align__(128) float g_W1t[HID * 512];     // W1 transposed: [n][k], K-major
__device__ __align__(128) float g_W2t[HID * HID];     // [Wm|Wv] transposed: [n][k]
__device__ __align__(128) float g_b2[HID];            // [bm | bv]
__device__ float g_dinv[NMAX];
__device__ int   g_cnt[NMAX];
__device__ int   g_rowptr[NMAX + 1];
__device__ int   g_cursor[NMAX];
__device__ int   g_csrc[EMAX];
__device__ int   g_bsum[1024];
__device__ int   g_boff[1024];
__device__ int   g_is64;

// ================= dtype detection =================
// int64 edges viewed as int32 -> odd words all zero; int32 edges -> random ids.
__global__ void k_detect(const int* __restrict__ EI32) {
    int v = EI32[threadIdx.x * 2 + 1];
    unsigned nz = __ballot_sync(0xffffffffu, v != 0);
    if (threadIdx.x == 0) g_is64 = (nz == 0) ? 1 : 0;
}

__device__ __forceinline__ int edge_read(const void* EI, int idx) {
    if (g_is64) return (int)((const long long*)EI)[idx];
    return ((const int*)EI)[idx];
}

// ================= CSR build =================

__global__ void k_zero_int(int* __restrict__ p, int n) {
    int i = blockIdx.x * blockDim.x + threadIdx.x;
    if (i < n) p[i] = 0;
}

__global__ void k_count(const void* __restrict__ EI, int* __restrict__ cnt, int E, int N) {
    int e = blockIdx.x * blockDim.x + threadIdx.x;
    if (e >= E) return;
    int d = edge_read(EI, E + e);
    if ((unsigned)d < (unsigned)N) atomicAdd(&cnt[d], 1);
}

// per-block sums of cnt (256/block)
__global__ void k_bsum(const int* __restrict__ cnt, int* __restrict__ bsum, int N) {
    __shared__ int red[8];
    int i = blockIdx.x * 256 + threadIdx.x;
    int lane = threadIdx.x & 31, w = threadIdx.x >> 5;
    int v = (i < N) ? cnt[i] : 0;
#pragma unroll
    for (int o = 16; o >= 1; o >>= 1) v += __shfl_down_sync(0xffffffffu, v, o);
    if (lane == 0) red[w] = v;
    __syncthreads();
    if (threadIdx.x == 0) {
        int s = 0;
#pragma unroll
        for (int j = 0; j < 8; j++) s += red[j];
        bsum[blockIdx.x] = s;
    }
}

// single-block exclusive scan of block sums (nb <= 1024)
__global__ __launch_bounds__(1024) void k_scan_bsum(const int* __restrict__ bsum,
                                                    int* __restrict__ boff, int nb) {
    __shared__ int wsum[32], woff[32];
    int t = threadIdx.x, lane = t & 31, w = t >> 5;
    int v = (t < nb) ? bsum[t] : 0;
    int incl = v;
#pragma unroll
    for (int o = 1; o < 32; o <<= 1) {
        int x = __shfl_up_sync(0xffffffffu, incl, o);
        if (lane >= o) incl += x;
    }
    if (lane == 31) wsum[w] = incl;
    __syncthreads();
    if (w == 0) {
        int ws = wsum[lane];
        int wi = ws;
#pragma unroll
        for (int o = 1; o < 32; o <<= 1) {
            int x = __shfl_up_sync(0xffffffffu, wi, o);
            if (lane >= o) wi += x;
        }
        woff[lane] = wi - ws;
    }
    __syncthreads();
    if (t < nb) boff[t] = incl - v + woff[w];
}

// final: rowptr/cursor = global exclusive scan; dinv = rsqrt(cnt+1)
__global__ void k_scan_final(const int* __restrict__ cnt, const int* __restrict__ boff,
                             int* __restrict__ rowptr, int* __restrict__ cursor,
                             float* __restrict__ dinv, int N) {
    __shared__ int wsum[8], woff2[8];
    int i = blockIdx.x * 256 + threadIdx.x;
    int t = threadIdx.x, lane = t & 31, w = t >> 5;
    int v = (i < N) ? cnt[i] : 0;
    int incl = v;
#pragma unroll
    for (int o = 1; o < 32; o <<= 1) {
        int x = __shfl_up_sync(0xffffffffu, incl, o);
        if (lane >= o) incl += x;
    }
    if (lane == 31) wsum[w] = incl;
    __syncthreads();
    if (t == 0) {
        int a = 0;
#pragma unroll
        for (int j = 0; j < 8; j++) { woff2[j] = a; a += wsum[j]; }
    }
    __syncthreads();
    if (i < N) {
        int excl = boff[blockIdx.x] + woff2[w] + incl - v;
        rowptr[i] = excl;
        cursor[i] = excl;
        dinv[i] = rsqrtf((float)v + 1.0f);
        if (i == N - 1) rowptr[N] = excl + v;
    }
}

__global__ void k_fill(const void* __restrict__ EI, int* __restrict__ cursor,
                       int* __restrict__ csrc, int E, int N) {
    int e = blockIdx.x * blockDim.x + threadIdx.x;
    if (e >= E) return;
    int s = edge_read(EI, e);
    int d = edge_read(EI, E + e);
    if ((unsigned)d >= (unsigned)N || (unsigned)s >= (unsigned)N) return;
    int pos = atomicAdd(&cursor[d], 1);
    if ((unsigned)pos < (unsigned)EMAX) csrc[pos] = s;
}

// ================= weight packing (transpose to [n][k] K-major) =================

__global__ void k_packW1t(const float* __restrict__ W1, float* __restrict__ W1t) {
    int idx = blockIdx.x * 256 + threadIdx.x;   // 128*512
    if (idx >= 128 * 512) return;
    int n = idx >> 9, k = idx & 511;
    W1t[idx] = W1[k * 128 + n];
}

__global__ void k_packW2t(const float* __restrict__ Wm, const float* __restrict__ bm,
                          const float* __restrict__ Wv, const float* __restrict__ bv,
                          float* __restrict__ W2t, float* __restrict__ b2) {
    int idx = blockIdx.x * 256 + threadIdx.x;   // 128*128
    if (idx < 128 * 128) {
        int n = idx >> 7, k = idx & 127;
        W2t[idx] = (n < 64) ? Wm[k * 64 + n] : Wv[k * 64 + (n - 64)];
    }
    if (idx < HID) b2[idx] = (idx < 64) ? bm[idx] : bv[idx - 64];
}

// ================= mma.sync 3xTF32 GEMM =================
// C[i,:128] = dinv[i] * (A[i,:K] @ Bt^T).  Bt stored [128][K] K-major.
// BM=128, BN=128, BK=16, 256 threads; warp grid 4x2, warp tile 32x64.
// Split: a = hi + lo, hi = a & 0xFFFFE000.  D += hi*hi + hi*lo + lo*hi.

__device__ __forceinline__ float tf32_hi(float a) {
    return __uint_as_float(__float_as_uint(a) & 0xFFFFE000u);
}

__device__ __forceinline__ void mma_tf32(float* c, const uint32_t* a, const uint32_t* b) {
    asm volatile(
        "mma.sync.aligned.m16n8k8.row.col.f32.tf32.tf32.f32 "
        "{%0,%1,%2,%3}, {%4,%5,%6,%7}, {%8,%9}, {%0,%1,%2,%3};"
        : "+f"(c[0]), "+f"(c[1]), "+f"(c[2]), "+f"(c[3])
        : "r"(a[0]), "r"(a[1]), "r"(a[2]), "r"(a[3]), "r"(b[0]), "r"(b[1]));
}

#define SPITCH 136   // floats per smem row: banks (k%4)*8 + qr -> conflict-free frags

template <int K>
__global__ __launch_bounds__(256) void k_gemm_mma(
    const float* __restrict__ A, const float* __restrict__ Bt,
    const float* __restrict__ dinv, float* __restrict__ C, int M)
{
    __shared__ float As_hi[16][SPITCH], As_lo[16][SPITCH];
    __shared__ float Bs_hi[16][SPITCH], Bs_lo[16][SPITCH];

    int t = threadIdx.x, lane = t & 31, wid = t >> 5;
    int warp_m = wid >> 1;   // 0..3
    int warp_n = wid & 1;    // 0..1
    int qr = lane >> 2;      // 0..7
    int qc = lane & 3;       // 0..3
    int r0 = blockIdx.x * 128;

    // global-load mapping: row = t>>1 (0..127), k-offset = (t&1)*8 (two float4)
    int grow = t >> 1;
    int gko  = (t & 1) * 8;
    int arow = r0 + grow;
    bool aval = (arow < M);
    const float4* Arow = reinterpret_cast<const float4*>(A + (size_t)arow * K);
    const float4* Brow = reinterpret_cast<const float4*>(Bt + (size_t)grow * K);

    float c[2][8][4];
#pragma unroll
    for (int mt = 0; mt < 2; mt++)
#pragma unroll
        for (int nt = 0; nt < 8; nt++)
#pragma unroll
            for (int j = 0; j < 4; j++) c[mt][nt][j] = 0.0f;

    for (int k0 = 0; k0 < K; k0 += 16) {
#pragma unroll
        for (int q = 0; q < 2; q++) {
            int kf = gko + q * 4;   // float offset within chunk
            float4 va = aval ? Arow[(k0 + kf) >> 2] : make_float4(0.f, 0.f, 0.f, 0.f);
            float4 vb = Brow[(k0 + kf) >> 2];
            float h;
            h = tf32_hi(va.x); As_hi[kf + 0][grow] = h; As_lo[kf + 0][grow] = va.x - h;
            h = tf32_hi(va.y); As_hi[kf + 1][grow] = h; As_lo[kf + 1][grow] = va.y - h;
            h = tf32_hi(va.z); As_hi[kf + 2][grow] = h; As_lo[kf + 2][grow] = va.z - h;
            h = tf32_hi(va.w); As_hi[kf + 3][grow] = h; As_lo[kf + 3][grow] = va.w - h;
            h = tf32_hi(vb.x); Bs_hi[kf + 0][grow] = h; Bs_lo[kf + 0][grow] = vb.x - h;
            h = tf32_hi(vb.y); Bs_hi[kf + 1][grow] = h; Bs_lo[kf + 1][grow] = vb.y - h;
            h = tf32_hi(vb.z); Bs_hi[kf + 2][grow] = h; Bs_lo[kf + 2][grow] = vb.z - h;
            h = tf32_hi(vb.w); Bs_hi[kf + 3][grow] = h; Bs_lo[kf + 3][grow] = vb.w - h;
        }
        __syncthreads();

#pragma unroll
        for (int ks = 0; ks < 16; ks += 8) {
            // A fragments for both m-tiles
            uint32_t ah[2][4], al[2][4];
#pragma unroll
            for (int mt = 0; mt < 2; mt++) {
                int m0 = warp_m * 32 + mt * 16 + qr;
                ah[mt][0] = __float_as_uint(As_hi[ks + qc][m0]);
                ah[mt][1] = __float_as_uint(As_hi[ks + qc][m0 + 8]);
                ah[mt][2] = __float_as_uint(As_hi[ks + qc + 4][m0]);
                ah[mt][3] = __float_as_uint(As_hi[ks + qc + 4][m0 + 8]);
                al[mt][0] = __float_as_uint(As_lo[ks + qc][m0]);
                al[mt][1] = __float_as_uint(As_lo[ks + qc][m0 + 8]);
                al[mt][2] = __float_as_uint(As_lo[ks + qc + 4][m0]);
                al[mt][3] = __float_as_uint(As_lo[ks + qc + 4][m0 + 8]);
            }
#pragma unroll
            for (int nt = 0; nt < 8; nt++) {
                int n0 = warp_n * 64 + nt * 8 + qr;
                uint32_t bh[2], bl[2];
                bh[0] = __float_as_uint(Bs_hi[ks + qc][n0]);
                bh[1] = __float_as_uint(Bs_hi[ks + qc + 4][n0]);
                bl[0] = __float_as_uint(Bs_lo[ks + qc][n0]);
                bl[1] = __float_as_uint(Bs_lo[ks + qc + 4][n0]);
#pragma unroll
                for (int mt = 0; mt < 2; mt++) {
                    mma_tf32(c[mt][nt], ah[mt], bh);
                    mma_tf32(c[mt][nt], ah[mt], bl);
                    mma_tf32(c[mt][nt], al[mt], bh);
                }
            }
        }
        __syncthreads();
    }

    // epilogue: scale by dinv[row], store float2 pairs
#pragma unroll
    for (int mt = 0; mt < 2; mt++) {
        int rlo = r0 + warp_m * 32 + mt * 16 + qr;
        int rhi = rlo + 8;
        float slo = (rlo < M) ? dinv[rlo] : 0.0f;
        float shi = (rhi < M) ? dinv[rhi] : 0.0f;
#pragma unroll
        for (int nt = 0; nt < 8; nt++) {
            int col = warp_n * 64 + nt * 8 + qc * 2;
            if (rlo < M) {
                float2 v = make_float2(c[mt][nt][0] * slo, c[mt][nt][1] * slo);
                *reinterpret_cast<float2*>(&C[(size_t)rlo * HID + col]) = v;
            }
            if (rhi < M) {
                float2 v = make_float2(c[mt][nt][2] * shi, c[mt][nt][3] * shi);
                *reinterpret_cast<float2*>(&C[(size_t)rhi * HID + col]) = v;
            }
        }
    }
}

// ================= gather aggregation + fused epilogue =================
// One warp per destination node. acc = Hs[d] (self loop) + sum Hs[src].
// MODE 0: out[d,:] = relu(acc*dinv[d] + bias)   (row-major N x 128)
// MODE 1: split write: cols [0,64) -> out[d*64..], cols [64,128) -> out[N*64 + d*64..]

template <int MODE>
__global__ __launch_bounds__(256) void k_gather(
    const int* __restrict__ rowptr, const int* __restrict__ csrc,
    const float* __restrict__ Hs, const float* __restrict__ dinv,
    const float* __restrict__ bias, float* __restrict__ out, int N)
{
    int w = (blockIdx.x * blockDim.x + threadIdx.x) >> 5;
    int lane = threadIdx.x & 31;
    if (w >= N) return;

    const float4* Hs4 = reinterpret_cast<const float4*>(Hs);
    float4 acc = Hs4[(size_t)w * 32 + lane];  // self loop

    int beg = rowptr[w], end = rowptr[w + 1];
    int e = beg;
    for (; e + 4 <= end; e += 4) {
        int s0 = csrc[e], s1 = csrc[e + 1], s2 = csrc[e + 2], s3 = csrc[e + 3];
        float4 v0 = Hs4[(size_t)s0 * 32 + lane];
        float4 v1 = Hs4[(size_t)s1 * 32 + lane];
        float4 v2 = Hs4[(size_t)s2 * 32 + lane];
        float4 v3 = Hs4[(size_t)s3 * 32 + lane];
        acc.x += v0.x + v1.x + v2.x + v3.x;
        acc.y += v0.y + v1.y + v2.y + v3.y;
        acc.z += v0.z + v1.z + v2.z + v3.z;
        acc.w += v0.w + v1.w + v2.w + v3.w;
    }
    for (; e < end; e++) {
        int s = csrc[e];
        float4 v = Hs4[(size_t)s * 32 + lane];
        acc.x += v.x; acc.y += v.y; acc.z += v.z; acc.w += v.w;
    }

    float sc = dinv[w];
    float4 b = reinterpret_cast<const float4*>(bias)[lane];
    float4 r;
    r.x = fmaf(acc.x, sc, b.x);
    r.y = fmaf(acc.y, sc, b.y);
    r.z = fmaf(acc.z, sc, b.z);
    r.w = fmaf(acc.w, sc, b.w);

    if (MODE == 0) {
        r.x = fmaxf(r.x, 0.f); r.y = fmaxf(r.y, 0.f);
        r.z = fmaxf(r.z, 0.f); r.w = fmaxf(r.w, 0.f);
        reinterpret_cast<float4*>(out)[(size_t)w * 32 + lane] = r;
    } else {
        int j0 = lane * 4;
        if (j0 < 64) {
            *reinterpret_cast<float4*>(&out[(size_t)w * 64 + j0]) = r;
        } else {
            *reinterpret_cast<float4*>(&out[(size_t)N * 64 + (size_t)w * 64 + (j0 - 64)]) = r;
        }
    }
}

// ================= launch =================

extern "C" void kernel_launch(void* const* d_in, const int* in_sizes, int n_in,
                              void* d_out, int out_size)
{
    const float* X  = (const float*)d_in[0];
    const void*  EI = d_in[1];
    const float* W1 = (const float*)d_in[2];
    const float* b1 = (const float*)d_in[3];
    const float* Wm = (const float*)d_in[4];
    const float* bm = (const float*)d_in[5];
    const float* Wv = (const float*)d_in[6];
    const float* bv = (const float*)d_in[7];
    float*       out = (float*)d_out;

    int N = in_sizes[0] / 512;
    int E = in_sizes[1] / 2;

    float *p_H, *p_H1, *p_W1t, *p_W2t, *p_b2, *p_dinv;
    int *p_cnt, *p_rowptr, *p_cursor, *p_csrc, *p_bs, *p_bo;
    cudaGetSymbolAddress((void**)&p_H,      g_H);
    cudaGetSymbolAddress((void**)&p_H1,     g_H1);
    cudaGetSymbolAddress((void**)&p_W1t,    g_W1t);
    cudaGetSymbolAddress((void**)&p_W2t,    g_W2t);
    cudaGetSymbolAddress((void**)&p_b2,     g_b2);
    cudaGetSymbolAddress((void**)&p_dinv,   g_dinv);
    cudaGetSymbolAddress((void**)&p_cnt,    g_cnt);
    cudaGetSymbolAddress((void**)&p_rowptr, g_rowptr);
    cudaGetSymbolAddress((void**)&p_cursor, g_cursor);
    cudaGetSymbolAddress((void**)&p_csrc,   g_csrc);
    cudaGetSymbolAddress((void**)&p_bs,     g_bsum);
    cudaGetSymbolAddress((void**)&p_bo,     g_boff);

    dim3 blk(256);
    int nb = (N + 255) / 256;

    // ---- dtype detect + CSR + degrees ----
    k_detect<<<1, 32>>>((const int*)EI);
    k_zero_int<<<nb, blk>>>(p_cnt, N);
    k_count<<<(E + 255) / 256, blk>>>(EI, p_cnt, E, N);
    k_bsum<<<nb, blk>>>(p_cnt, p_bs, N);
    k_scan_bsum<<<1, 1024>>>(p_bs, p_bo, nb);
    k_scan_final<<<nb, blk>>>(p_cnt, p_bo, p_rowptr, p_cursor, p_dinv, N);
    k_fill<<<(E + 255) / 256, blk>>>(EI, p_cursor, p_csrc, E, N);
    k_packW1t<<<(128 * 512 + 255) / 256, blk>>>(W1, p_W1t);
    k_packW2t<<<(128 * 128 + 255) / 256, blk>>>(Wm, bm, Wv, bv, p_W2t, p_b2);

    // ---- Layer 1: Hs = dinv * (X @ W1); h1 = relu(gather(Hs)*dinv + b1) ----
    k_gemm_mma<512><<<(N + 127) / 128, blk>>>(X, p_W1t, p_dinv, p_H, N);
    k_gather<0><<<(N * 32 + 255) / 256, blk>>>(p_rowptr, p_csrc, p_H, p_dinv, b1, p_H1, N);

    // ---- Layer 2 (mean|var fused): out = gather(dinv * h1 @ [Wm|Wv]) ----
    k_gemm_mma<128><<<(N + 127) / 128, blk>>>(p_H1, p_W2t, p_dinv, p_H, N);
    k_gather<1><<<(N * 32 + 255) / 256, blk>>>(p_rowptr, p_csrc, p_H, p_dinv, p_b2, out, N);
}

// round 10
// speedup vs baseline: 1.1967x; 1.0679x over previous
#include <cuda_runtime.h>
#include <cuda_fp16.h>
#include <cstdint>

#define HID 128
#define NMAX 100000
#define EMAX 3200000

// ---- static scratch (no allocation allowed) ----
__device__ __align__(128) __half g_Hh[NMAX * HID];    // fp16 dinv-prescaled transformed rows
__device__ __align__(128) float g_H1[NMAX * HID];     // h1 after layer-1 gather (fp32)
__device__ __align__(128) float g_W1t[HID * 512];     // W1 transposed: [n][k], K-major
__device__ __align__(128) float g_W2t[HID * HID];     // [Wm|Wv] transposed: [n][k]
__device__ __align__(128) float g_b2[HID];            // [bm | bv]
__device__ float g_dinv[NMAX];
__device__ int   g_cnt[NMAX];
__device__ int   g_rowptr[NMAX + 1];
__device__ int   g_cursor[NMAX];
__device__ int   g_csrc[EMAX];
__device__ int   g_bsum[1024];
__device__ int   g_boff[1024];
__device__ int   g_is64;

// ================= dtype detect + zero (merged) =================
// int64 edges viewed as int32 -> odd words all zero; int32 edges -> random ids.
// (E = 3.2M >> 32, so reading the first 64 int32 words is always in-bounds.)
__global__ void k_zero_detect(const int* __restrict__ EI32, int* __restrict__ cnt, int n) {
    int i = blockIdx.x * blockDim.x + threadIdx.x;
    if (i < n) cnt[i] = 0;
    if (blockIdx.x == 0 && threadIdx.x < 32) {
        int v = EI32[threadIdx.x * 2 + 1];
        unsigned nz = __ballot_sync(0xffffffffu, v != 0);
        if (threadIdx.x == 0) g_is64 = (nz == 0) ? 1 : 0;
    }
}

__device__ __forceinline__ int edge_read(const void* EI, int idx) {
    if (g_is64) return (int)((const long long*)EI)[idx];
    return ((const int*)EI)[idx];
}

// ================= CSR build =================

__global__ void k_count(const void* __restrict__ EI, int* __restrict__ cnt, int E, int N) {
    int e = blockIdx.x * blockDim.x + threadIdx.x;
    if (e >= E) return;
    int d = edge_read(EI, E + e);
    if ((unsigned)d < (unsigned)N) atomicAdd(&cnt[d], 1);
}

__global__ void k_bsum(const int* __restrict__ cnt, int* __restrict__ bsum, int N) {
    __shared__ int red[8];
    int i = blockIdx.x * 256 + threadIdx.x;
    int lane = threadIdx.x & 31, w = threadIdx.x >> 5;
    int v = (i < N) ? cnt[i] : 0;
#pragma unroll
    for (int o = 16; o >= 1; o >>= 1) v += __shfl_down_sync(0xffffffffu, v, o);
    if (lane == 0) red[w] = v;
    __syncthreads();
    if (threadIdx.x == 0) {
        int s = 0;
#pragma unroll
        for (int j = 0; j < 8; j++) s += red[j];
        bsum[blockIdx.x] = s;
    }
}

__global__ __launch_bounds__(1024) void k_scan_bsum(const int* __restrict__ bsum,
                                                    int* __restrict__ boff, int nb) {
    __shared__ int wsum[32], woff[32];
    int t = threadIdx.x, lane = t & 31, w = t >> 5;
    int v = (t < nb) ? bsum[t] : 0;
    int incl = v;
#pragma unroll
    for (int o = 1; o < 32; o <<= 1) {
        int x = __shfl_up_sync(0xffffffffu, incl, o);
        if (lane >= o) incl += x;
    }
    if (lane == 31) wsum[w] = incl;
    __syncthreads();
    if (w == 0) {
        int ws = wsum[lane];
        int wi = ws;
#pragma unroll
        for (int o = 1; o < 32; o <<= 1) {
            int x = __shfl_up_sync(0xffffffffu, wi, o);
            if (lane >= o) wi += x;
        }
        woff[lane] = wi - ws;
    }
    __syncthreads();
    if (t < nb) boff[t] = incl - v + woff[w];
}

__global__ void k_scan_final(const int* __restrict__ cnt, const int* __restrict__ boff,
                             int* __restrict__ rowptr, int* __restrict__ cursor,
                             float* __restrict__ dinv, int N) {
    __shared__ int wsum[8], woff2[8];
    int i = blockIdx.x * 256 + threadIdx.x;
    int t = threadIdx.x, lane = t & 31, w = t >> 5;
    int v = (i < N) ? cnt[i] : 0;
    int incl = v;
#pragma unroll
    for (int o = 1; o < 32; o <<= 1) {
        int x = __shfl_up_sync(0xffffffffu, incl, o);
        if (lane >= o) incl += x;
    }
    if (lane == 31) wsum[w] = incl;
    __syncthreads();
    if (t == 0) {
        int a = 0;
#pragma unroll
        for (int j = 0; j < 8; j++) { woff2[j] = a; a += wsum[j]; }
    }
    __syncthreads();
    if (i < N) {
        int excl = boff[blockIdx.x] + woff2[w] + incl - v;
        rowptr[i] = excl;
        cursor[i] = excl;
        dinv[i] = rsqrtf((float)v + 1.0f);
        if (i == N - 1) rowptr[N] = excl + v;
    }
}

__global__ void k_fill(const void* __restrict__ EI, int* __restrict__ cursor,
                       int* __restrict__ csrc, int E, int N) {
    int e = blockIdx.x * blockDim.x + threadIdx.x;
    if (e >= E) return;
    int s = edge_read(EI, e);
    int d = edge_read(EI, E + e);
    if ((unsigned)d >= (unsigned)N || (unsigned)s >= (unsigned)N) return;
    int pos = atomicAdd(&cursor[d], 1);
    if ((unsigned)pos < (unsigned)EMAX) csrc[pos] = s;
}

// ================= weight packing (transpose to [n][k] K-major) =================

__global__ void k_packW1t(const float* __restrict__ W1, float* __restrict__ W1t) {
    int idx = blockIdx.x * 256 + threadIdx.x;   // 128*512
    if (idx >= 128 * 512) return;
    int n = idx >> 9, k = idx & 511;
    W1t[idx] = W1[k * 128 + n];
}

__global__ void k_packW2t(const float* __restrict__ Wm, const float* __restrict__ bm,
                          const float* __restrict__ Wv, const float* __restrict__ bv,
                          float* __restrict__ W2t, float* __restrict__ b2) {
    int idx = blockIdx.x * 256 + threadIdx.x;   // 128*128
    if (idx < 128 * 128) {
        int n = idx >> 7, k = idx & 127;
        W2t[idx] = (n < 64) ? Wm[k * 64 + n] : Wv[k * 64 + (n - 64)];
    }
    if (idx < HID) b2[idx] = (idx < 64) ? bm[idx] : bv[idx - 64];
}

// ================= mma.sync 3xTF32 GEMM =================
// Ch[i,:128] = fp16( dinv[i] * (A[i,:K] @ Bt^T) ).  Bt stored [128][K] K-major.
// BM=128, BN=128, BK=16, 256 threads; warp grid 4x2, warp tile 32x64.
// Split: a = hi + lo, hi = a & 0xFFFFE000.  D += hi*hi + hi*lo + lo*hi.

__device__ __forceinline__ float tf32_hi(float a) {
    return __uint_as_float(__float_as_uint(a) & 0xFFFFE000u);
}

__device__ __forceinline__ void mma_tf32(float* c, const uint32_t* a, const uint32_t* b) {
    asm volatile(
        "mma.sync.aligned.m16n8k8.row.col.f32.tf32.tf32.f32 "
        "{%0,%1,%2,%3}, {%4,%5,%6,%7}, {%8,%9}, {%0,%1,%2,%3};"
        : "+f"(c[0]), "+f"(c[1]), "+f"(c[2]), "+f"(c[3])
        : "r"(a[0]), "r"(a[1]), "r"(a[2]), "r"(a[3]), "r"(b[0]), "r"(b[1]));
}

#define SPITCH 136

template <int K>
__global__ __launch_bounds__(256) void k_gemm_mma(
    const float* __restrict__ A, const float* __restrict__ Bt,
    const float* __restrict__ dinv, __half* __restrict__ C, int M)
{
    __shared__ float As_hi[16][SPITCH], As_lo[16][SPITCH];
    __shared__ float Bs_hi[16][SPITCH], Bs_lo[16][SPITCH];

    int t = threadIdx.x, lane = t & 31, wid = t >> 5;
    int warp_m = wid >> 1;
    int warp_n = wid & 1;
    int qr = lane >> 2;
    int qc = lane & 3;
    int r0 = blockIdx.x * 128;

    int grow = t >> 1;
    int gko  = (t & 1) * 8;
    int arow = r0 + grow;
    bool aval = (arow < M);
    const float4* Arow = reinterpret_cast<const float4*>(A + (size_t)arow * K);
    const float4* Brow = reinterpret_cast<const float4*>(Bt + (size_t)grow * K);

    float c[2][8][4];
#pragma unroll
    for (int mt = 0; mt < 2; mt++)
#pragma unroll
        for (int nt = 0; nt < 8; nt++)
#pragma unroll
            for (int j = 0; j < 4; j++) c[mt][nt][j] = 0.0f;

    for (int k0 = 0; k0 < K; k0 += 16) {
#pragma unroll
        for (int q = 0; q < 2; q++) {
            int kf = gko + q * 4;
            float4 va = aval ? Arow[(k0 + kf) >> 2] : make_float4(0.f, 0.f, 0.f, 0.f);
            float4 vb = Brow[(k0 + kf) >> 2];
            float h;
            h = tf32_hi(va.x); As_hi[kf + 0][grow] = h; As_lo[kf + 0][grow] = va.x - h;
            h = tf32_hi(va.y); As_hi[kf + 1][grow] = h; As_lo[kf + 1][grow] = va.y - h;
            h = tf32_hi(va.z); As_hi[kf + 2][grow] = h; As_lo[kf + 2][grow] = va.z - h;
            h = tf32_hi(va.w); As_hi[kf + 3][grow] = h; As_lo[kf + 3][grow] = va.w - h;
            h = tf32_hi(vb.x); Bs_hi[kf + 0][grow] = h; Bs_lo[kf + 0][grow] = vb.x - h;
            h = tf32_hi(vb.y); Bs_hi[kf + 1][grow] = h; Bs_lo[kf + 1][grow] = vb.y - h;
            h = tf32_hi(vb.z); Bs_hi[kf + 2][grow] = h; Bs_lo[kf + 2][grow] = vb.z - h;
            h = tf32_hi(vb.w); Bs_hi[kf + 3][grow] = h; Bs_lo[kf + 3][grow] = vb.w - h;
        }
        __syncthreads();

#pragma unroll
        for (int ks = 0; ks < 16; ks += 8) {
            uint32_t ah[2][4], al[2][4];
#pragma unroll
            for (int mt = 0; mt < 2; mt++) {
                int m0 = warp_m * 32 + mt * 16 + qr;
                ah[mt][0] = __float_as_uint(As_hi[ks + qc][m0]);
                ah[mt][1] = __float_as_uint(As_hi[ks + qc][m0 + 8]);
                ah[mt][2] = __float_as_uint(As_hi[ks + qc + 4][m0]);
                ah[mt][3] = __float_as_uint(As_hi[ks + qc + 4][m0 + 8]);
                al[mt][0] = __float_as_uint(As_lo[ks + qc][m0]);
                al[mt][1] = __float_as_uint(As_lo[ks + qc][m0 + 8]);
                al[mt][2] = __float_as_uint(As_lo[ks + qc + 4][m0]);
                al[mt][3] = __float_as_uint(As_lo[ks + qc + 4][m0 + 8]);
            }
#pragma unroll
            for (int nt = 0; nt < 8; nt++) {
                int n0 = warp_n * 64 + nt * 8 + qr;
                uint32_t bh[2], bl[2];
                bh[0] = __float_as_uint(Bs_hi[ks + qc][n0]);
                bh[1] = __float_as_uint(Bs_hi[ks + qc + 4][n0]);
                bl[0] = __float_as_uint(Bs_lo[ks + qc][n0]);
                bl[1] = __float_as_uint(Bs_lo[ks + qc + 4][n0]);
#pragma unroll
                for (int mt = 0; mt < 2; mt++) {
                    mma_tf32(c[mt][nt], ah[mt], bh);
                    mma_tf32(c[mt][nt], ah[mt], bl);
                    mma_tf32(c[mt][nt], al[mt], bh);
                }
            }
        }
        __syncthreads();
    }

    // epilogue: scale by dinv[row], convert to fp16, store half2 pairs
#pragma unroll
    for (int mt = 0; mt < 2; mt++) {
        int rlo = r0 + warp_m * 32 + mt * 16 + qr;
        int rhi = rlo + 8;
        float slo = (rlo < M) ? dinv[rlo] : 0.0f;
        float shi = (rhi < M) ? dinv[rhi] : 0.0f;
#pragma unroll
        for (int nt = 0; nt < 8; nt++) {
            int col = warp_n * 64 + nt * 8 + qc * 2;
            if (rlo < M) {
                __half2 v = __floats2half2_rn(c[mt][nt][0] * slo, c[mt][nt][1] * slo);
                *reinterpret_cast<__half2*>(&C[(size_t)rlo * HID + col]) = v;
            }
            if (rhi < M) {
                __half2 v = __floats2half2_rn(c[mt][nt][2] * shi, c[mt][nt][3] * shi);
                *reinterpret_cast<__half2*>(&C[(size_t)rhi * HID + col]) = v;
            }
        }
    }
}

// ================= gather aggregation (fp16 table, fp32 accum) =================
// One warp per destination node; lane handles 4 halves (uint2 = 8 bytes; 32*8=256B row).
// MODE 0: out[d,:] = relu(acc*dinv[d] + bias)   (fp32, row-major N x 128)
// MODE 1: split write: cols [0,64) -> out[d*64..], cols [64,128) -> out[N*64 + d*64..]

__device__ __forceinline__ float4 h4_to_f4(uint2 raw) {
    __half2 h0 = *reinterpret_cast<__half2*>(&raw.x);
    __half2 h1 = *reinterpret_cast<__half2*>(&raw.y);
    float2 f0 = __half22float2(h0);
    float2 f1 = __half22float2(h1);
    return make_float4(f0.x, f0.y, f1.x, f1.y);
}

template <int MODE>
__global__ __launch_bounds__(256) void k_gather(
    const int* __restrict__ rowptr, const int* __restrict__ csrc,
    const __half* __restrict__ Hs, const float* __restrict__ dinv,
    const float* __restrict__ bias, float* __restrict__ out, int N)
{
    int w = (blockIdx.x * blockDim.x + threadIdx.x) >> 5;
    int lane = threadIdx.x & 31;
    if (w >= N) return;

    const uint2* Hs2 = reinterpret_cast<const uint2*>(Hs);
    float4 acc = h4_to_f4(Hs2[(size_t)w * 32 + lane]);  // self loop

    int beg = rowptr[w], end = rowptr[w + 1];
    int e = beg;
    for (; e + 4 <= end; e += 4) {
        int s0 = csrc[e], s1 = csrc[e + 1], s2 = csrc[e + 2], s3 = csrc[e + 3];
        float4 v0 = h4_to_f4(Hs2[(size_t)s0 * 32 + lane]);
        float4 v1 = h4_to_f4(Hs2[(size_t)s1 * 32 + lane]);
        float4 v2 = h4_to_f4(Hs2[(size_t)s2 * 32 + lane]);
        float4 v3 = h4_to_f4(Hs2[(size_t)s3 * 32 + lane]);
        acc.x += v0.x + v1.x + v2.x + v3.x;
        acc.y += v0.y + v1.y + v2.y + v3.y;
        acc.z += v0.z + v1.z + v2.z + v3.z;
        acc.w += v0.w + v1.w + v2.w + v3.w;
    }
    for (; e < end; e++) {
        int s = csrc[e];
        float4 v = h4_to_f4(Hs2[(size_t)s * 32 + lane]);
        acc.x += v.x; acc.y += v.y; acc.z += v.z; acc.w += v.w;
    }

    float sc = dinv[w];
    float4 b = reinterpret_cast<const float4*>(bias)[lane];
    float4 r;
    r.x = fmaf(acc.x, sc, b.x);
    r.y = fmaf(acc.y, sc, b.y);
    r.z = fmaf(acc.z, sc, b.z);
    r.w = fmaf(acc.w, sc, b.w);

    if (MODE == 0) {
        r.x = fmaxf(r.x, 0.f); r.y = fmaxf(r.y, 0.f);
        r.z = fmaxf(r.z, 0.f); r.w = fmaxf(r.w, 0.f);
        reinterpret_cast<float4*>(out)[(size_t)w * 32 + lane] = r;
    } else {
        int j0 = lane * 4;
        if (j0 < 64) {
            *reinterpret_cast<float4*>(&out[(size_t)w * 64 + j0]) = r;
        } else {
            *reinterpret_cast<float4*>(&out[(size_t)N * 64 + (size_t)w * 64 + (j0 - 64)]) = r;
        }
    }
}

// ================= launch =================

extern "C" void kernel_launch(void* const* d_in, const int* in_sizes, int n_in,
                              void* d_out, int out_size)
{
    const float* X  = (const float*)d_in[0];
    const void*  EI = d_in[1];
    const float* W1 = (const float*)d_in[2];
    const float* b1 = (const float*)d_in[3];
    const float* Wm = (const float*)d_in[4];
    const float* bm = (const float*)d_in[5];
    const float* Wv = (const float*)d_in[6];
    const float* bv = (const float*)d_in[7];
    float*       out = (float*)d_out;

    int N = in_sizes[0] / 512;
    int E = in_sizes[1] / 2;

    float *p_H1, *p_W1t, *p_W2t, *p_b2, *p_dinv;
    __half* p_Hh;
    int *p_cnt, *p_rowptr, *p_cursor, *p_csrc, *p_bs, *p_bo;
    cudaGetSymbolAddress((void**)&p_Hh,     g_Hh);
    cudaGetSymbolAddress((void**)&p_H1,     g_H1);
    cudaGetSymbolAddress((void**)&p_W1t,    g_W1t);
    cudaGetSymbolAddress((void**)&p_W2t,    g_W2t);
    cudaGetSymbolAddress((void**)&p_b2,     g_b2);
    cudaGetSymbolAddress((void**)&p_dinv,   g_dinv);
    cudaGetSymbolAddress((void**)&p_cnt,    g_cnt);
    cudaGetSymbolAddress((void**)&p_rowptr, g_rowptr);
    cudaGetSymbolAddress((void**)&p_cursor, g_cursor);
    cudaGetSymbolAddress((void**)&p_csrc,   g_csrc);
    cudaGetSymbolAddress((void**)&p_bs,     g_bsum);
    cudaGetSymbolAddress((void**)&p_bo,     g_boff);

    dim3 blk(256);
    int nb = (N + 255) / 256;

    // ---- dtype detect + CSR + degrees ----
    k_zero_detect<<<nb, blk>>>((const int*)EI, p_cnt, N);
    k_count<<<(E + 255) / 256, blk>>>(EI, p_cnt, E, N);
    k_bsum<<<nb, blk>>>(p_cnt, p_bs, N);
    k_scan_bsum<<<1, 1024>>>(p_bs, p_bo, nb);
    k_scan_final<<<nb, blk>>>(p_cnt, p_bo, p_rowptr, p_cursor, p_dinv, N);
    k_fill<<<(E + 255) / 256, blk>>>(EI, p_cursor, p_csrc, E, N);
    k_packW1t<<<(128 * 512 + 255) / 256, blk>>>(W1, p_W1t);
    k_packW2t<<<(128 * 128 + 255) / 256, blk>>>(Wm, bm, Wv, bv, p_W2t, p_b2);

    // ---- Layer 1: Hh = fp16(dinv * (X @ W1)); h1 = relu(gather(Hh)*dinv + b1) ----
    k_gemm_mma<512><<<(N + 127) / 128, blk>>>(X, p_W1t, p_dinv, p_Hh, N);
    k_gather<0><<<(N * 32 + 255) / 256, blk>>>(p_rowptr, p_csrc, p_Hh, p_dinv, b1, p_H1, N);

    // ---- Layer 2 (mean|var fused) ----
    k_gemm_mma<128><<<(N + 127) / 128, blk>>>(p_H1, p_W2t, p_dinv, p_Hh, N);
    k_gather<1><<<(N * 32 + 255) / 256, blk>>>(p_rowptr, p_csrc, p_Hh, p_dinv, p_b2, out, N);
}

// round 11
// speedup vs baseline: 1.2523x; 1.0464x over previous
#include <cuda_runtime.h>
#include <cuda_fp16.h>
#include <cstdint>

#define HID 128
#define NMAX 100000
#define EMAX 3200000

// ---- static scratch (no allocation allowed) ----
__device__ __align__(128) __half g_Hh[NMAX * HID];    // fp16 transformed rows (UNscaled)
__device__ __align__(128) float g_H1[NMAX * HID];     // h1 after layer-1 gather (fp32)
__device__ __align__(128) float g_W1t[HID * 512];     // W1 transposed: [n][k], K-major
__device__ __align__(128) float g_W2t[HID * HID];     // [Wm|Wv] transposed: [n][k]
__device__ __align__(128) float g_b2[HID];            // [bm | bv]
__device__ float g_dinv[NMAX];
__device__ int   g_cnt[NMAX];
__device__ int   g_rowptr[NMAX + 1];
__device__ int   g_cursor[NMAX];
__device__ int   g_csrc[EMAX];
__device__ int   g_bsum[1024];
__device__ int   g_boff[1024];
__device__ int   g_is64;

// ================= dtype detect + zero (merged) =================
// int64 edges viewed as int32 -> odd words all zero; int32 edges -> random ids.
__global__ void k_zero_detect(const int* __restrict__ EI32, int* __restrict__ cnt, int n) {
    int i = blockIdx.x * blockDim.x + threadIdx.x;
    if (i < n) cnt[i] = 0;
    if (blockIdx.x == 0 && threadIdx.x < 32) {
        int v = EI32[threadIdx.x * 2 + 1];
        unsigned nz = __ballot_sync(0xffffffffu, v != 0);
        if (threadIdx.x == 0) g_is64 = (nz == 0) ? 1 : 0;
    }
}

__device__ __forceinline__ int edge_read(const void* EI, int idx) {
    if (g_is64) return (int)((const long long*)EI)[idx];
    return ((const int*)EI)[idx];
}

// ================= CSR build =================

__global__ void k_count(const void* __restrict__ EI, int* __restrict__ cnt, int E, int N) {
    int e = blockIdx.x * blockDim.x + threadIdx.x;
    if (e >= E) return;
    int d = edge_read(EI, E + e);
    if ((unsigned)d < (unsigned)N) atomicAdd(&cnt[d], 1);
}

__global__ void k_bsum(const int* __restrict__ cnt, int* __restrict__ bsum, int N) {
    __shared__ int red[8];
    int i = blockIdx.x * 256 + threadIdx.x;
    int lane = threadIdx.x & 31, w = threadIdx.x >> 5;
    int v = (i < N) ? cnt[i] : 0;
#pragma unroll
    for (int o = 16; o >= 1; o >>= 1) v += __shfl_down_sync(0xffffffffu, v, o);
    if (lane == 0) red[w] = v;
    __syncthreads();
    if (threadIdx.x == 0) {
        int s = 0;
#pragma unroll
        for (int j = 0; j < 8; j++) s += red[j];
        bsum[blockIdx.x] = s;
    }
}

__global__ __launch_bounds__(1024) void k_scan_bsum(const int* __restrict__ bsum,
                                                    int* __restrict__ boff, int nb) {
    __shared__ int wsum[32], woff[32];
    int t = threadIdx.x, lane = t & 31, w = t >> 5;
    int v = (t < nb) ? bsum[t] : 0;
    int incl = v;
#pragma unroll
    for (int o = 1; o < 32; o <<= 1) {
        int x = __shfl_up_sync(0xffffffffu, incl, o);
        if (lane >= o) incl += x;
    }
    if (lane == 31) wsum[w] = incl;
    __syncthreads();
    if (w == 0) {
        int ws = wsum[lane];
        int wi = ws;
#pragma unroll
        for (int o = 1; o < 32; o <<= 1) {
            int x = __shfl_up_sync(0xffffffffu, wi, o);
            if (lane >= o) wi += x;
        }
        woff[lane] = wi - ws;
    }
    __syncthreads();
    if (t < nb) boff[t] = incl - v + woff[w];
}

__global__ void k_scan_final(const int* __restrict__ cnt, const int* __restrict__ boff,
                             int* __restrict__ rowptr, int* __restrict__ cursor,
                             float* __restrict__ dinv, int N) {
    __shared__ int wsum[8], woff2[8];
    int i = blockIdx.x * 256 + threadIdx.x;
    int t = threadIdx.x, lane = t & 31, w = t >> 5;
    int v = (i < N) ? cnt[i] : 0;
    int incl = v;
#pragma unroll
    for (int o = 1; o < 32; o <<= 1) {
        int x = __shfl_up_sync(0xffffffffu, incl, o);
        if (lane >= o) incl += x;
    }
    if (lane == 31) wsum[w] = incl;
    __syncthreads();
    if (t == 0) {
        int a = 0;
#pragma unroll
        for (int j = 0; j < 8; j++) { woff2[j] = a; a += wsum[j]; }
    }
    __syncthreads();
    if (i < N) {
        int excl = boff[blockIdx.x] + woff2[w] + incl - v;
        rowptr[i] = excl;
        cursor[i] = excl;
        dinv[i] = rsqrtf((float)v + 1.0f);
        if (i == N - 1) rowptr[N] = excl + v;
    }
}

__global__ void k_fill(const void* __restrict__ EI, int* __restrict__ cursor,
                       int* __restrict__ csrc, int E, int N) {
    int e = blockIdx.x * blockDim.x + threadIdx.x;
    if (e >= E) return;
    int s = edge_read(EI, e);
    int d = edge_read(EI, E + e);
    if ((unsigned)d >= (unsigned)N || (unsigned)s >= (unsigned)N) return;
    int pos = atomicAdd(&cursor[d], 1);
    if ((unsigned)pos < (unsigned)EMAX) csrc[pos] = s;
}

// ================= weight packing (transpose to [n][k] K-major) =================

__global__ void k_packW1t(const float* __restrict__ W1, float* __restrict__ W1t) {
    int idx = blockIdx.x * 256 + threadIdx.x;   // 128*512
    if (idx >= 128 * 512) return;
    int n = idx >> 9, k = idx & 511;
    W1t[idx] = W1[k * 128 + n];
}

__global__ void k_packW2t(const float* __restrict__ Wm, const float* __restrict__ bm,
                          const float* __restrict__ Wv, const float* __restrict__ bv,
                          float* __restrict__ W2t, float* __restrict__ b2) {
    int idx = blockIdx.x * 256 + threadIdx.x;   // 128*128
    if (idx < 128 * 128) {
        int n = idx >> 7, k = idx & 127;
        W2t[idx] = (n < 64) ? Wm[k * 64 + n] : Wv[k * 64 + (n - 64)];
    }
    if (idx < HID) b2[idx] = (idx < 64) ? bm[idx] : bv[idx - 64];
}

// ================= mma.sync 3xTF32 GEMM (no dinv scale) =================
// Ch[i,:128] = fp16( A[i,:K] @ Bt^T ).  Bt stored [128][K] K-major.
// BM=128, BN=128, BK=16, 256 threads; warp grid 4x2, warp tile 32x64.

__device__ __forceinline__ float tf32_hi(float a) {
    return __uint_as_float(__float_as_uint(a) & 0xFFFFE000u);
}

__device__ __forceinline__ void mma_tf32(float* c, const uint32_t* a, const uint32_t* b) {
    asm volatile(
        "mma.sync.aligned.m16n8k8.row.col.f32.tf32.tf32.f32 "
        "{%0,%1,%2,%3}, {%4,%5,%6,%7}, {%8,%9}, {%0,%1,%2,%3};"
        : "+f"(c[0]), "+f"(c[1]), "+f"(c[2]), "+f"(c[3])
        : "r"(a[0]), "r"(a[1]), "r"(a[2]), "r"(a[3]), "r"(b[0]), "r"(b[1]));
}

#define SPITCH 136

template <int K>
__global__ __launch_bounds__(256) void k_gemm_mma(
    const float* __restrict__ A, const float* __restrict__ Bt,
    __half* __restrict__ C, int M)
{
    __shared__ float As_hi[16][SPITCH], As_lo[16][SPITCH];
    __shared__ float Bs_hi[16][SPITCH], Bs_lo[16][SPITCH];

    int t = threadIdx.x, lane = t & 31, wid = t >> 5;
    int warp_m = wid >> 1;
    int warp_n = wid & 1;
    int qr = lane >> 2;
    int qc = lane & 3;
    int r0 = blockIdx.x * 128;

    int grow = t >> 1;
    int gko  = (t & 1) * 8;
    int arow = r0 + grow;
    bool aval = (arow < M);
    const float4* Arow = reinterpret_cast<const float4*>(A + (size_t)arow * K);
    const float4* Brow = reinterpret_cast<const float4*>(Bt + (size_t)grow * K);

    float c[2][8][4];
#pragma unroll
    for (int mt = 0; mt < 2; mt++)
#pragma unroll
        for (int nt = 0; nt < 8; nt++)
#pragma unroll
            for (int j = 0; j < 4; j++) c[mt][nt][j] = 0.0f;

    for (int k0 = 0; k0 < K; k0 += 16) {
#pragma unroll
        for (int q = 0; q < 2; q++) {
            int kf = gko + q * 4;
            float4 va = aval ? Arow[(k0 + kf) >> 2] : make_float4(0.f, 0.f, 0.f, 0.f);
            float4 vb = Brow[(k0 + kf) >> 2];
            float h;
            h = tf32_hi(va.x); As_hi[kf + 0][grow] = h; As_lo[kf + 0][grow] = va.x - h;
            h = tf32_hi(va.y); As_hi[kf + 1][grow] = h; As_lo[kf + 1][grow] = va.y - h;
            h = tf32_hi(va.z); As_hi[kf + 2][grow] = h; As_lo[kf + 2][grow] = va.z - h;
            h = tf32_hi(va.w); As_hi[kf + 3][grow] = h; As_lo[kf + 3][grow] = va.w - h;
            h = tf32_hi(vb.x); Bs_hi[kf + 0][grow] = h; Bs_lo[kf + 0][grow] = vb.x - h;
            h = tf32_hi(vb.y); Bs_hi[kf + 1][grow] = h; Bs_lo[kf + 1][grow] = vb.y - h;
            h = tf32_hi(vb.z); Bs_hi[kf + 2][grow] = h; Bs_lo[kf + 2][grow] = vb.z - h;
            h = tf32_hi(vb.w); Bs_hi[kf + 3][grow] = h; Bs_lo[kf + 3][grow] = vb.w - h;
        }
        __syncthreads();

#pragma unroll
        for (int ks = 0; ks < 16; ks += 8) {
            uint32_t ah[2][4], al[2][4];
#pragma unroll
            for (int mt = 0; mt < 2; mt++) {
                int m0 = warp_m * 32 + mt * 16 + qr;
                ah[mt][0] = __float_as_uint(As_hi[ks + qc][m0]);
                ah[mt][1] = __float_as_uint(As_hi[ks + qc][m0 + 8]);
                ah[mt][2] = __float_as_uint(As_hi[ks + qc + 4][m0]);
                ah[mt][3] = __float_as_uint(As_hi[ks + qc + 4][m0 + 8]);
                al[mt][0] = __float_as_uint(As_lo[ks + qc][m0]);
                al[mt][1] = __float_as_uint(As_lo[ks + qc][m0 + 8]);
                al[mt][2] = __float_as_uint(As_lo[ks + qc + 4][m0]);
                al[mt][3] = __float_as_uint(As_lo[ks + qc + 4][m0 + 8]);
            }
#pragma unroll
            for (int nt = 0; nt < 8; nt++) {
                int n0 = warp_n * 64 + nt * 8 + qr;
                uint32_t bh[2], bl[2];
                bh[0] = __float_as_uint(Bs_hi[ks + qc][n0]);
                bh[1] = __float_as_uint(Bs_hi[ks + qc + 4][n0]);
                bl[0] = __float_as_uint(Bs_lo[ks + qc][n0]);
                bl[1] = __float_as_uint(Bs_lo[ks + qc + 4][n0]);
#pragma unroll
                for (int mt = 0; mt < 2; mt++) {
                    mma_tf32(c[mt][nt], ah[mt], bh);
                    mma_tf32(c[mt][nt], ah[mt], bl);
                    mma_tf32(c[mt][nt], al[mt], bh);
                }
            }
        }
        __syncthreads();
    }

    // epilogue: convert to fp16 (no scaling), store half2 pairs
#pragma unroll
    for (int mt = 0; mt < 2; mt++) {
        int rlo = r0 + warp_m * 32 + mt * 16 + qr;
        int rhi = rlo + 8;
#pragma unroll
        for (int nt = 0; nt < 8; nt++) {
            int col = warp_n * 64 + nt * 8 + qc * 2;
            if (rlo < M) {
                __half2 v = __floats2half2_rn(c[mt][nt][0], c[mt][nt][1]);
                *reinterpret_cast<__half2*>(&C[(size_t)rlo * HID + col]) = v;
            }
            if (rhi < M) {
                __half2 v = __floats2half2_rn(c[mt][nt][2], c[mt][nt][3]);
                *reinterpret_cast<__half2*>(&C[(size_t)rhi * HID + col]) = v;
            }
        }
    }
}

// ================= gather aggregation (fp16 table, per-edge dinv scale) =================
// One warp per destination node. acc = dinv[w]*H[w] + sum dinv[s]*H[s]; r = acc*dinv[w]+b.
// MODE 0: out[d,:] = relu(r)   (fp32, row-major N x 128)
// MODE 1: split write: cols [0,64) -> out[d*64..], cols [64,128) -> out[N*64 + d*64..]

__device__ __forceinline__ float4 h4_to_f4(uint2 raw) {
    __half2 h0 = *reinterpret_cast<__half2*>(&raw.x);
    __half2 h1 = *reinterpret_cast<__half2*>(&raw.y);
    float2 f0 = __half22float2(h0);
    float2 f1 = __half22float2(h1);
    return make_float4(f0.x, f0.y, f1.x, f1.y);
}

template <int MODE>
__global__ __launch_bounds__(256) void k_gather(
    const int* __restrict__ rowptr, const int* __restrict__ csrc,
    const __half* __restrict__ Hs, const float* __restrict__ dinv,
    const float* __restrict__ bias, float* __restrict__ out, int N)
{
    int w = (blockIdx.x * blockDim.x + threadIdx.x) >> 5;
    int lane = threadIdx.x & 31;
    if (w >= N) return;

    const uint2* Hs2 = reinterpret_cast<const uint2*>(Hs);
    float sw = dinv[w];
    float4 vs = h4_to_f4(Hs2[(size_t)w * 32 + lane]);  // self loop
    float4 acc = make_float4(vs.x * sw, vs.y * sw, vs.z * sw, vs.w * sw);

    int beg = rowptr[w], end = rowptr[w + 1];
    int e = beg;
    for (; e + 4 <= end; e += 4) {
        int s0 = csrc[e], s1 = csrc[e + 1], s2 = csrc[e + 2], s3 = csrc[e + 3];
        float d0 = dinv[s0], d1 = dinv[s1], d2 = dinv[s2], d3 = dinv[s3];
        float4 v0 = h4_to_f4(Hs2[(size_t)s0 * 32 + lane]);
        float4 v1 = h4_to_f4(Hs2[(size_t)s1 * 32 + lane]);
        float4 v2 = h4_to_f4(Hs2[(size_t)s2 * 32 + lane]);
        float4 v3 = h4_to_f4(Hs2[(size_t)s3 * 32 + lane]);
        acc.x = fmaf(v0.x, d0, fmaf(v1.x, d1, fmaf(v2.x, d2, fmaf(v3.x, d3, acc.x))));
        acc.y = fmaf(v0.y, d0, fmaf(v1.y, d1, fmaf(v2.y, d2, fmaf(v3.y, d3, acc.y))));
        acc.z = fmaf(v0.z, d0, fmaf(v1.z, d1, fmaf(v2.z, d2, fmaf(v3.z, d3, acc.z))));
        acc.w = fmaf(v0.w, d0, fmaf(v1.w, d1, fmaf(v2.w, d2, fmaf(v3.w, d3, acc.w))));
    }
    for (; e < end; e++) {
        int s = csrc[e];
        float ds = dinv[s];
        float4 v = h4_to_f4(Hs2[(size_t)s * 32 + lane]);
        acc.x = fmaf(v.x, ds, acc.x);
        acc.y = fmaf(v.y, ds, acc.y);
        acc.z = fmaf(v.z, ds, acc.z);
        acc.w = fmaf(v.w, ds, acc.w);
    }

    float4 b = reinterpret_cast<const float4*>(bias)[lane];
    float4 r;
    r.x = fmaf(acc.x, sw, b.x);
    r.y = fmaf(acc.y, sw, b.y);
    r.z = fmaf(acc.z, sw, b.z);
    r.w = fmaf(acc.w, sw, b.w);

    if (MODE == 0) {
        r.x = fmaxf(r.x, 0.f); r.y = fmaxf(r.y, 0.f);
        r.z = fmaxf(r.z, 0.f); r.w = fmaxf(r.w, 0.f);
        reinterpret_cast<float4*>(out)[(size_t)w * 32 + lane] = r;
    } else {
        int j0 = lane * 4;
        if (j0 < 64) {
            *reinterpret_cast<float4*>(&out[(size_t)w * 64 + j0]) = r;
        } else {
            *reinterpret_cast<float4*>(&out[(size_t)N * 64 + (size_t)w * 64 + (j0 - 64)]) = r;
        }
    }
}

// ================= launch =================

extern "C" void kernel_launch(void* const* d_in, const int* in_sizes, int n_in,
                              void* d_out, int out_size)
{
    const float* X  = (const float*)d_in[0];
    const void*  EI = d_in[1];
    const float* W1 = (const float*)d_in[2];
    const float* b1 = (const float*)d_in[3];
    const float* Wm = (const float*)d_in[4];
    const float* bm = (const float*)d_in[5];
    const float* Wv = (const float*)d_in[6];
    const float* bv = (const float*)d_in[7];
    float*       out = (float*)d_out;

    int N = in_sizes[0] / 512;
    int E = in_sizes[1] / 2;

    float *p_H1, *p_W1t, *p_W2t, *p_b2, *p_dinv;
    __half* p_Hh;
    int *p_cnt, *p_rowptr, *p_cursor, *p_csrc, *p_bs, *p_bo;
    cudaGetSymbolAddress((void**)&p_Hh,     g_Hh);
    cudaGetSymbolAddress((void**)&p_H1,     g_H1);
    cudaGetSymbolAddress((void**)&p_W1t,    g_W1t);
    cudaGetSymbolAddress((void**)&p_W2t,    g_W2t);
    cudaGetSymbolAddress((void**)&p_b2,     g_b2);
    cudaGetSymbolAddress((void**)&p_dinv,   g_dinv);
    cudaGetSymbolAddress((void**)&p_cnt,    g_cnt);
    cudaGetSymbolAddress((void**)&p_rowptr, g_rowptr);
    cudaGetSymbolAddress((void**)&p_cursor, g_cursor);
    cudaGetSymbolAddress((void**)&p_csrc,   g_csrc);
    cudaGetSymbolAddress((void**)&p_bs,     g_bsum);
    cudaGetSymbolAddress((void**)&p_bo,     g_boff);

    dim3 blk(256);
    int nb = (N + 255) / 256;

    // fork/join: edge branch (CSR) runs concurrently with feature branch (packs + GEMM1)
    cudaStream_t s2;
    cudaEvent_t ev0, evA;
    cudaStreamCreateWithFlags(&s2, cudaStreamNonBlocking);
    cudaEventCreateWithFlags(&ev0, cudaEventDisableTiming);
    cudaEventCreateWithFlags(&evA, cudaEventDisableTiming);

    cudaEventRecord(ev0, 0);
    cudaStreamWaitEvent(s2, ev0, 0);

    // ---- Branch A (stream s2): dtype detect + CSR + degrees ----
    k_zero_detect<<<nb, blk, 0, s2>>>((const int*)EI, p_cnt, N);
    k_count<<<(E + 255) / 256, blk, 0, s2>>>(EI, p_cnt, E, N);
    k_bsum<<<nb, blk, 0, s2>>>(p_cnt, p_bs, N);
    k_scan_bsum<<<1, 1024, 0, s2>>>(p_bs, p_bo, nb);
    k_scan_final<<<nb, blk, 0, s2>>>(p_cnt, p_bo, p_rowptr, p_cursor, p_dinv, N);
    k_fill<<<(E + 255) / 256, blk, 0, s2>>>(EI, p_cursor, p_csrc, E, N);
    cudaEventRecord(evA, s2);

    // ---- Branch B (main stream): weight packs + GEMM1 (unscaled) ----
    k_packW1t<<<(128 * 512 + 255) / 256, blk>>>(W1, p_W1t);
    k_packW2t<<<(128 * 128 + 255) / 256, blk>>>(Wm, bm, Wv, bv, p_W2t, p_b2);
    k_gemm_mma<512><<<(N + 127) / 128, blk>>>(X, p_W1t, p_Hh, N);

    // ---- join ----
    cudaStreamWaitEvent(0, evA, 0);

    // ---- Layer 1 gather: h1 = relu(dinv*(gather dinv[s]*H[s] + dinv*H) + b1) ----
    k_gather<0><<<(N * 32 + 255) / 256, blk>>>(p_rowptr, p_csrc, p_Hh, p_dinv, b1, p_H1, N);

    // ---- Layer 2 (mean|var fused) ----
    k_gemm_mma<128><<<(N + 127) / 128, blk>>>(p_H1, p_W2t, p_Hh, N);
    k_gather<1><<<(N * 32 + 255) / 256, blk>>>(p_rowptr, p_csrc, p_Hh, p_dinv, p_b2, out, N);
}

// round 12
// speedup vs baseline: 1.5177x; 1.2119x over previous
#include <cuda_runtime.h>
#include <cuda_fp16.h>
#include <cstdint>

#define HID 128
#define NMAX 100000
#define EMAX 3200000

// ---- static scratch (no allocation allowed) ----
__device__ __align__(128) __half g_Hh[NMAX * HID];    // fp16 transformed rows (UNscaled)
__device__ __align__(128) float g_H1[NMAX * HID];     // h1 after layer-1 gather (fp32)
__device__ __align__(128) float g_W1t[HID * 512];     // W1^T [n][k], tf32-rounded
__device__ __align__(128) float g_W2t[HID * HID];     // [Wm|Wv]^T [n][k], tf32-rounded
__device__ __align__(128) float g_b2[HID];            // [bm | bv]
__device__ float g_dinv[NMAX];
__device__ int   g_cnt[NMAX];
__device__ int   g_rowptr[NMAX + 1];
__device__ int   g_cursor[NMAX];
__device__ int   g_csrc[EMAX];
__device__ int   g_bsum[1024];
__device__ int   g_boff[1024];
__device__ int   g_is64;

__device__ __forceinline__ float to_tf32_rna(float a) {
    float r;
    asm("cvt.rna.tf32.f32 %0, %1;" : "=f"(r) : "f"(a));
    return r;
}

// ================= dtype detect + zero (merged) =================
__global__ void k_zero_detect(const int* __restrict__ EI32, int* __restrict__ cnt, int n) {
    int i = blockIdx.x * blockDim.x + threadIdx.x;
    if (i < n) cnt[i] = 0;
    if (blockIdx.x == 0 && threadIdx.x < 32) {
        int v = EI32[threadIdx.x * 2 + 1];
        unsigned nz = __ballot_sync(0xffffffffu, v != 0);
        if (threadIdx.x == 0) g_is64 = (nz == 0) ? 1 : 0;
    }
}

__device__ __forceinline__ int edge_read(const void* EI, int idx) {
    if (g_is64) return (int)((const long long*)EI)[idx];
    return ((const int*)EI)[idx];
}

// ================= CSR build =================

__global__ void k_count(const void* __restrict__ EI, int* __restrict__ cnt, int E, int N) {
    int e = blockIdx.x * blockDim.x + threadIdx.x;
    if (e >= E) return;
    int d = edge_read(EI, E + e);
    if ((unsigned)d < (unsigned)N) atomicAdd(&cnt[d], 1);
}

__global__ void k_bsum(const int* __restrict__ cnt, int* __restrict__ bsum, int N) {
    __shared__ int red[8];
    int i = blockIdx.x * 256 + threadIdx.x;
    int lane = threadIdx.x & 31, w = threadIdx.x >> 5;
    int v = (i < N) ? cnt[i] : 0;
#pragma unroll
    for (int o = 16; o >= 1; o >>= 1) v += __shfl_down_sync(0xffffffffu, v, o);
    if (lane == 0) red[w] = v;
    __syncthreads();
    if (threadIdx.x == 0) {
        int s = 0;
#pragma unroll
        for (int j = 0; j < 8; j++) s += red[j];
        bsum[blockIdx.x] = s;
    }
}

__global__ __launch_bounds__(1024) void k_scan_bsum(const int* __restrict__ bsum,
                                                    int* __restrict__ boff, int nb) {
    __shared__ int wsum[32], woff[32];
    int t = threadIdx.x, lane = t & 31, w = t >> 5;
    int v = (t < nb) ? bsum[t] : 0;
    int incl = v;
#pragma unroll
    for (int o = 1; o < 32; o <<= 1) {
        int x = __shfl_up_sync(0xffffffffu, incl, o);
        if (lane >= o) incl += x;
    }
    if (lane == 31) wsum[w] = incl;
    __syncthreads();
    if (w == 0) {
        int ws = wsum[lane];
        int wi = ws;
#pragma unroll
        for (int o = 1; o < 32; o <<= 1) {
            int x = __shfl_up_sync(0xffffffffu, wi, o);
            if (lane >= o) wi += x;
        }
        woff[lane] = wi - ws;
    }
    __syncthreads();
    if (t < nb) boff[t] = incl - v + woff[w];
}

__global__ void k_scan_final(const int* __restrict__ cnt, const int* __restrict__ boff,
                             int* __restrict__ rowptr, int* __restrict__ cursor,
                             float* __restrict__ dinv, int N) {
    __shared__ int wsum[8], woff2[8];
    int i = blockIdx.x * 256 + threadIdx.x;
    int t = threadIdx.x, lane = t & 31, w = t >> 5;
    int v = (i < N) ? cnt[i] : 0;
    int incl = v;
#pragma unroll
    for (int o = 1; o < 32; o <<= 1) {
        int x = __shfl_up_sync(0xffffffffu, incl, o);
        if (lane >= o) incl += x;
    }
    if (lane == 31) wsum[w] = incl;
    __syncthreads();
    if (t == 0) {
        int a = 0;
#pragma unroll
        for (int j = 0; j < 8; j++) { woff2[j] = a; a += wsum[j]; }
    }
    __syncthreads();
    if (i < N) {
        int excl = boff[blockIdx.x] + woff2[w] + incl - v;
        rowptr[i] = excl;
        cursor[i] = excl;
        dinv[i] = rsqrtf((float)v + 1.0f);
        if (i == N - 1) rowptr[N] = excl + v;
    }
}

__global__ void k_fill(const void* __restrict__ EI, int* __restrict__ cursor,
                       int* __restrict__ csrc, int E, int N) {
    int e = blockIdx.x * blockDim.x + threadIdx.x;
    if (e >= E) return;
    int s = edge_read(EI, e);
    int d = edge_read(EI, E + e);
    if ((unsigned)d >= (unsigned)N || (unsigned)s >= (unsigned)N) return;
    int pos = atomicAdd(&cursor[d], 1);
    if ((unsigned)pos < (unsigned)EMAX) csrc[pos] = s;
}

// ============ weight packing (transpose to [n][k], tf32-rounded) ============

__global__ void k_packW1t(const float* __restrict__ W1, float* __restrict__ W1t) {
    int idx = blockIdx.x * 256 + threadIdx.x;   // 128*512
    if (idx >= 128 * 512) return;
    int n = idx >> 9, k = idx & 511;
    W1t[idx] = to_tf32_rna(W1[k * 128 + n]);
}

__global__ void k_packW2t(const float* __restrict__ Wm, const float* __restrict__ bm,
                          const float* __restrict__ Wv, const float* __restrict__ bv,
                          float* __restrict__ W2t, float* __restrict__ b2) {
    int idx = blockIdx.x * 256 + threadIdx.x;   // 128*128
    if (idx < 128 * 128) {
        int n = idx >> 7, k = idx & 127;
        W2t[idx] = to_tf32_rna((n < 64) ? Wm[k * 64 + n] : Wv[k * 64 + (n - 64)]);
    }
    if (idx < HID) b2[idx] = (idx < 64) ? bm[idx] : bv[idx - 64];
}

// ================= mma.sync 2xTF32 GEMM =================
// Ch[i,:128] = fp16( A[i,:K] @ Bt^T ).  Bt [128][K] K-major, pre-rounded tf32.
// A split: a = hi + lo (truncation).  D = hi*B + lo*B (exact in A, B tf32-quantized).
// BM=128, BN=128, BK=16, 256 threads; warp grid 4x2, warp tile 32x64.

__device__ __forceinline__ float tf32_hi(float a) {
    return __uint_as_float(__float_as_uint(a) & 0xFFFFE000u);
}

__device__ __forceinline__ void mma_tf32(float* c, const uint32_t* a, const uint32_t* b) {
    asm volatile(
        "mma.sync.aligned.m16n8k8.row.col.f32.tf32.tf32.f32 "
        "{%0,%1,%2,%3}, {%4,%5,%6,%7}, {%8,%9}, {%0,%1,%2,%3};"
        : "+f"(c[0]), "+f"(c[1]), "+f"(c[2]), "+f"(c[3])
        : "r"(a[0]), "r"(a[1]), "r"(a[2]), "r"(a[3]), "r"(b[0]), "r"(b[1]));
}

#define SPITCH 136

template <int K>
__global__ __launch_bounds__(256) void k_gemm_mma(
    const float* __restrict__ A, const float* __restrict__ Bt,
    __half* __restrict__ C, int M)
{
    __shared__ float As_hi[16][SPITCH], As_lo[16][SPITCH];
    __shared__ float Bs[16][SPITCH];

    int t = threadIdx.x, lane = t & 31, wid = t >> 5;
    int warp_m = wid >> 1;
    int warp_n = wid & 1;
    int qr = lane >> 2;
    int qc = lane & 3;
    int r0 = blockIdx.x * 128;

    int grow = t >> 1;
    int gko  = (t & 1) * 8;
    int arow = r0 + grow;
    bool aval = (arow < M);
    const float4* Arow = reinterpret_cast<const float4*>(A + (size_t)arow * K);
    const float4* Brow = reinterpret_cast<const float4*>(Bt + (size_t)grow * K);

    float c[2][8][4];
#pragma unroll
    for (int mt = 0; mt < 2; mt++)
#pragma unroll
        for (int nt = 0; nt < 8; nt++)
#pragma unroll
            for (int j = 0; j < 4; j++) c[mt][nt][j] = 0.0f;

    for (int k0 = 0; k0 < K; k0 += 16) {
#pragma unroll
        for (int q = 0; q < 2; q++) {
            int kf = gko + q * 4;
            float4 va = aval ? Arow[(k0 + kf) >> 2] : make_float4(0.f, 0.f, 0.f, 0.f);
            float4 vb = Brow[(k0 + kf) >> 2];
            float h;
            h = tf32_hi(va.x); As_hi[kf + 0][grow] = h; As_lo[kf + 0][grow] = va.x - h;
            h = tf32_hi(va.y); As_hi[kf + 1][grow] = h; As_lo[kf + 1][grow] = va.y - h;
            h = tf32_hi(va.z); As_hi[kf + 2][grow] = h; As_lo[kf + 2][grow] = va.z - h;
            h = tf32_hi(va.w); As_hi[kf + 3][grow] = h; As_lo[kf + 3][grow] = va.w - h;
            Bs[kf + 0][grow] = vb.x;
            Bs[kf + 1][grow] = vb.y;
            Bs[kf + 2][grow] = vb.z;
            Bs[kf + 3][grow] = vb.w;
        }
        __syncthreads();

#pragma unroll
        for (int ks = 0; ks < 16; ks += 8) {
            uint32_t ah[2][4], al[2][4];
#pragma unroll
            for (int mt = 0; mt < 2; mt++) {
                int m0 = warp_m * 32 + mt * 16 + qr;
                ah[mt][0] = __float_as_uint(As_hi[ks + qc][m0]);
                ah[mt][1] = __float_as_uint(As_hi[ks + qc][m0 + 8]);
                ah[mt][2] = __float_as_uint(As_hi[ks + qc + 4][m0]);
                ah[mt][3] = __float_as_uint(As_hi[ks + qc + 4][m0 + 8]);
                al[mt][0] = __float_as_uint(As_lo[ks + qc][m0]);
                al[mt][1] = __float_as_uint(As_lo[ks + qc][m0 + 8]);
                al[mt][2] = __float_as_uint(As_lo[ks + qc + 4][m0]);
                al[mt][3] = __float_as_uint(As_lo[ks + qc + 4][m0 + 8]);
            }
#pragma unroll
            for (int nt = 0; nt < 8; nt++) {
                int n0 = warp_n * 64 + nt * 8 + qr;
                uint32_t bh[2];
                bh[0] = __float_as_uint(Bs[ks + qc][n0]);
                bh[1] = __float_as_uint(Bs[ks + qc + 4][n0]);
#pragma unroll
                for (int mt = 0; mt < 2; mt++) {
                    mma_tf32(c[mt][nt], ah[mt], bh);
                    mma_tf32(c[mt][nt], al[mt], bh);
                }
            }
        }
        __syncthreads();
    }

    // epilogue: convert to fp16, store half2 pairs
#pragma unroll
    for (int mt = 0; mt < 2; mt++) {
        int rlo = r0 + warp_m * 32 + mt * 16 + qr;
        int rhi = rlo + 8;
#pragma unroll
        for (int nt = 0; nt < 8; nt++) {
            int col = warp_n * 64 + nt * 8 + qc * 2;
            if (rlo < M) {
                __half2 v = __floats2half2_rn(c[mt][nt][0], c[mt][nt][1]);
                *reinterpret_cast<__half2*>(&C[(size_t)rlo * HID + col]) = v;
            }
            if (rhi < M) {
                __half2 v = __floats2half2_rn(c[mt][nt][2], c[mt][nt][3]);
                *reinterpret_cast<__half2*>(&C[(size_t)rhi * HID + col]) = v;
            }
        }
    }
}

// ======== gather aggregation: warp/node, 2 edges per iteration (uint4) ========
// fp16 row = 256B = 16 lanes x uint4. Lanes 0-15 edge e, lanes 16-31 edge e+1.
// acc = dinv[w]*H[w] + sum dinv[s]*H[s]; r = acc*dinv[w]+b. Cross-half shfl reduce.
// MODE 0: out[d,:] = relu(r)  (fp32 N x 128);  MODE 1: mean|var split.

template <int MODE>
__global__ __launch_bounds__(256) void k_gather(
    const int* __restrict__ rowptr, const int* __restrict__ csrc,
    const __half* __restrict__ Hs, const float* __restrict__ dinv,
    const float* __restrict__ bias, float* __restrict__ out, int N)
{
    int w = (blockIdx.x * blockDim.x + threadIdx.x) >> 5;
    int lane = threadIdx.x & 31;
    int half = lane >> 4;      // 0 or 1
    int hl = lane & 15;        // lane within half; covers cols [hl*8, hl*8+8)
    if (w >= N) return;

    const uint4* HsRow = reinterpret_cast<const uint4*>(Hs);  // 16 uint4 per row

    float acc[8];
#pragma unroll
    for (int j = 0; j < 8; j++) acc[j] = 0.0f;

    float sw = dinv[w];

    // self loop (half 0 only)
    if (half == 0) {
        uint4 raw = HsRow[(size_t)w * 16 + hl];
        const __half2* h2 = reinterpret_cast<const __half2*>(&raw);
#pragma unroll
        for (int j = 0; j < 4; j++) {
            float2 f = __half22float2(h2[j]);
            acc[j * 2 + 0] = fmaf(f.x, sw, acc[j * 2 + 0]);
            acc[j * 2 + 1] = fmaf(f.y, sw, acc[j * 2 + 1]);
        }
    }

    int beg = rowptr[w], end = rowptr[w + 1];
    int e = beg;
    // 4 edges per iteration (2 per half)
    for (; e + 4 <= end; e += 4) {
        int sA = csrc[e + half];
        int sB = csrc[e + 2 + half];
        float dA = dinv[sA], dB = dinv[sB];
        uint4 rA = HsRow[(size_t)sA * 16 + hl];
        uint4 rB = HsRow[(size_t)sB * 16 + hl];
        const __half2* hA = reinterpret_cast<const __half2*>(&rA);
        const __half2* hB = reinterpret_cast<const __half2*>(&rB);
#pragma unroll
        for (int j = 0; j < 4; j++) {
            float2 fA = __half22float2(hA[j]);
            float2 fB = __half22float2(hB[j]);
            acc[j * 2 + 0] = fmaf(fA.x, dA, fmaf(fB.x, dB, acc[j * 2 + 0]));
            acc[j * 2 + 1] = fmaf(fA.y, dA, fmaf(fB.y, dB, acc[j * 2 + 1]));
        }
    }
    // 2 edges (1 per half)
    for (; e + 2 <= end; e += 2) {
        int s = csrc[e + half];
        float ds = dinv[s];
        uint4 raw = HsRow[(size_t)s * 16 + hl];
        const __half2* h2 = reinterpret_cast<const __half2*>(&raw);
#pragma unroll
        for (int j = 0; j < 4; j++) {
            float2 f = __half22float2(h2[j]);
            acc[j * 2 + 0] = fmaf(f.x, ds, acc[j * 2 + 0]);
            acc[j * 2 + 1] = fmaf(f.y, ds, acc[j * 2 + 1]);
        }
    }
    // odd tail (half 0 only)
    if (e < end && half == 0) {
        int s = csrc[e];
        float ds = dinv[s];
        uint4 raw = HsRow[(size_t)s * 16 + hl];
        const __half2* h2 = reinterpret_cast<const __half2*>(&raw);
#pragma unroll
        for (int j = 0; j < 4; j++) {
            float2 f = __half22float2(h2[j]);
            acc[j * 2 + 0] = fmaf(f.x, ds, acc[j * 2 + 0]);
            acc[j * 2 + 1] = fmaf(f.y, ds, acc[j * 2 + 1]);
        }
    }

    // cross-half reduction: lanes L and L+16 hold partial sums of same cols
#pragma unroll
    for (int j = 0; j < 8; j++)
        acc[j] += __shfl_xor_sync(0xffffffffu, acc[j], 16);

    // epilogue: half h writes float4 at cols hl*8 + h*4
    int j0 = hl * 8 + half * 4;
    const float4 b = *reinterpret_cast<const float4*>(&bias[j0]);
    int o = half * 4;
    float4 r;
    r.x = fmaf(acc[o + 0], sw, b.x);
    r.y = fmaf(acc[o + 1], sw, b.y);
    r.z = fmaf(acc[o + 2], sw, b.z);
    r.w = fmaf(acc[o + 3], sw, b.w);

    if (MODE == 0) {
        r.x = fmaxf(r.x, 0.f); r.y = fmaxf(r.y, 0.f);
        r.z = fmaxf(r.z, 0.f); r.w = fmaxf(r.w, 0.f);
        *reinterpret_cast<float4*>(&out[(size_t)w * HID + j0]) = r;
    } else {
        if (j0 < 64) {
            *reinterpret_cast<float4*>(&out[(size_t)w * 64 + j0]) = r;
        } else {
            *reinterpret_cast<float4*>(&out[(size_t)N * 64 + (size_t)w * 64 + (j0 - 64)]) = r;
        }
    }
}

// ================= launch =================

extern "C" void kernel_launch(void* const* d_in, const int* in_sizes, int n_in,
                              void* d_out, int out_size)
{
    const float* X  = (const float*)d_in[0];
    const void*  EI = d_in[1];
    const float* W1 = (const float*)d_in[2];
    const float* b1 = (const float*)d_in[3];
    const float* Wm = (const float*)d_in[4];
    const float* bm = (const float*)d_in[5];
    const float* Wv = (const float*)d_in[6];
    const float* bv = (const float*)d_in[7];
    float*       out = (float*)d_out;

    int N = in_sizes[0] / 512;
    int E = in_sizes[1] / 2;

    float *p_H1, *p_W1t, *p_W2t, *p_b2, *p_dinv;
    __half* p_Hh;
    int *p_cnt, *p_rowptr, *p_cursor, *p_csrc, *p_bs, *p_bo;
    cudaGetSymbolAddress((void**)&p_Hh,     g_Hh);
    cudaGetSymbolAddress((void**)&p_H1,     g_H1);
    cudaGetSymbolAddress((void**)&p_W1t,    g_W1t);
    cudaGetSymbolAddress((void**)&p_W2t,    g_W2t);
    cudaGetSymbolAddress((void**)&p_b2,     g_b2);
    cudaGetSymbolAddress((void**)&p_dinv,   g_dinv);
    cudaGetSymbolAddress((void**)&p_cnt,    g_cnt);
    cudaGetSymbolAddress((void**)&p_rowptr, g_rowptr);
    cudaGetSymbolAddress((void**)&p_cursor, g_cursor);
    cudaGetSymbolAddress((void**)&p_csrc,   g_csrc);
    cudaGetSymbolAddress((void**)&p_bs,     g_bsum);
    cudaGetSymbolAddress((void**)&p_bo,     g_boff);

    dim3 blk(256);
    int nb = (N + 255) / 256;

    // fork/join: edge branch (CSR) runs concurrently with feature branch (packs + GEMM1)
    cudaStream_t s2;
    cudaEvent_t ev0, evA;
    cudaStreamCreateWithFlags(&s2, cudaStreamNonBlocking);
    cudaEventCreateWithFlags(&ev0, cudaEventDisableTiming);
    cudaEventCreateWithFlags(&evA, cudaEventDisableTiming);

    cudaEventRecord(ev0, 0);
    cudaStreamWaitEvent(s2, ev0, 0);

    // ---- Branch A (stream s2): dtype detect + CSR + degrees ----
    k_zero_detect<<<nb, blk, 0, s2>>>((const int*)EI, p_cnt, N);
    k_count<<<(E + 255) / 256, blk, 0, s2>>>(EI, p_cnt, E, N);
    k_bsum<<<nb, blk, 0, s2>>>(p_cnt, p_bs, N);
    k_scan_bsum<<<1, 1024, 0, s2>>>(p_bs, p_bo, nb);
    k_scan_final<<<nb, blk, 0, s2>>>(p_cnt, p_bo, p_rowptr, p_cursor, p_dinv, N);
    k_fill<<<(E + 255) / 256, blk, 0, s2>>>(EI, p_cursor, p_csrc, E, N);
    cudaEventRecord(evA, s2);

    // ---- Branch B (main stream): weight packs + GEMM1 (unscaled) ----
    k_packW1t<<<(128 * 512 + 255) / 256, blk>>>(W1, p_W1t);
    k_packW2t<<<(128 * 128 + 255) / 256, blk>>>(Wm, bm, Wv, bv, p_W2t, p_b2);
    k_gemm_mma<512><<<(N + 127) / 128, blk>>>(X, p_W1t, p_Hh, N);

    // ---- join ----
    cudaStreamWaitEvent(0, evA, 0);

    // ---- Layer 1 gather ----
    k_gather<0><<<(N * 32 + 255) / 256, blk>>>(p_rowptr, p_csrc, p_Hh, p_dinv, b1, p_H1, N);

    // ---- Layer 2 (mean|var fused) ----
    k_gemm_mma<128><<<(N + 127) / 128, blk>>>(p_H1, p_W2t, p_Hh, N);
    k_gather<1><<<(N * 32 + 255) / 256, blk>>>(p_rowptr, p_csrc, p_Hh, p_dinv, p_b2, out, N);
}